// round 2
// baseline (speedup 1.0000x reference)
#include <cuda_runtime.h>
#include <math_constants.h>

// Problem constants (B=8, S=1024, V=32000)
#define BB 8
#define SS 1024
#define VV 32000
#define V4 (VV / 4)            // 8000 float4 per logits row
#define NVERIFY BB             // 8 verify blocks (one per batch row)
#define NGATHER 64             // 64 gather blocks * 1024 thr = 65536 >= 64000 float4
#define NBLK (NVERIFY + NGATHER)

// Device scratch (zero-initialized at module load; self-reset at end of kernel).
__device__ int          g_bonus_pos[BB];
__device__ volatile int g_ready[BB];
__device__ int          g_done;

// Output layout (float32, tuple order):
//   [0 .. B*S)               draft        (8192)
//   [B*S .. B*S+B)           num_newly    (8)
//   [B*S+B .. B*S+2B)        num_acc      (8)
//   [B*S+2B .. +B*V)         last_logits  (256000)
#define OFF_NEWLY   (BB * SS)
#define OFF_ACC     (BB * SS + BB)
#define OFF_LOGITS  (BB * SS + 2 * BB)

__global__ __launch_bounds__(1024) void eagle_fused_kernel(
    const int*   __restrict__ input_ids,   // [B, S]
    const float* __restrict__ logits,      // [B, S, V]
    const int*   __restrict__ npa,         // [B]
    float*       __restrict__ out)
{
    const int tid = threadIdx.x;

    if (blockIdx.x < NVERIFY) {
        // ================= VERIFY (one block per batch row) =================
        const int b    = blockIdx.x;
        const int lane = tid & 31;
        const int warp = tid >> 5;

        __shared__ float s_val[32];
        __shared__ int   s_idx[32];
        __shared__ int   s_cont;
        __shared__ int   s_bonus;

        const int* ids = input_ids + b * SS;

        // Prefetch draft source id (coalesced 4KB row) — overlaps npa latency.
        int myid = (tid < SS - 1) ? ids[tid + 1] : 0;

        const int start = npa[b] - 1;
        int k = start;

        for (;;) {
            const float4* row =
                (const float4*)(logits + ((size_t)b * SS + (size_t)k) * VV);

            // Expected next token (broadcast cacheline; overlaps row loads).
            int expect = (k < SS - 1) ? ids[k + 1] : -1;

            // ---- block argmax, MLP=8 front-batched loads ----
            float4 v[8];
            #pragma unroll
            for (int j = 0; j < 7; j++) v[j] = row[tid + j * 1024];
            const bool tail = (tid + 7 * 1024) < V4;
            if (tail) v[7] = row[tid + 7 * 1024];

            float best = -CUDART_INF_F;
            int   bidx = 0x7fffffff;
            #pragma unroll
            for (int j = 0; j < 8; j++) {
                if (j < 7 || tail) {
                    const int base = (tid + j * 1024) * 4;
                    const float4 w = v[j];
                    // increasing index order + strict '>' => first-occurrence max
                    if (w.x > best) { best = w.x; bidx = base;     }
                    if (w.y > best) { best = w.y; bidx = base + 1; }
                    if (w.z > best) { best = w.z; bidx = base + 2; }
                    if (w.w > best) { best = w.w; bidx = base + 3; }
                }
            }
            // warp reduce (val desc, idx asc on ties)
            #pragma unroll
            for (int off = 16; off > 0; off >>= 1) {
                float ov = __shfl_down_sync(0xffffffffu, best, off);
                int   oi = __shfl_down_sync(0xffffffffu, bidx, off);
                if (ov > best || (ov == best && oi < bidx)) { best = ov; bidx = oi; }
            }
            if (lane == 0) { s_val[warp] = best; s_idx[warp] = bidx; }
            __syncthreads();

            if (warp == 0) {
                float v0 = s_val[lane];
                int   i0 = s_idx[lane];
                #pragma unroll
                for (int off = 16; off > 0; off >>= 1) {
                    float ov = __shfl_down_sync(0xffffffffu, v0, off);
                    int   oi = __shfl_down_sync(0xffffffffu, i0, off);
                    if (ov > v0 || (ov == v0 && oi < i0)) { v0 = ov; i0 = oi; }
                }
                if (lane == 0) {
                    if (k < SS - 1 && i0 == expect) {
                        s_cont = 1;
                    } else {
                        s_cont  = 0;
                        s_bonus = i0;
                        // Signal the gather blocks ASAP (before epilogue).
                        g_bonus_pos[b] = k;
                        asm volatile("st.release.gpu.b32 [%0], %1;"
                                     :: "l"((int*)&g_ready[b]), "r"(1) : "memory");
                        out[OFF_NEWLY + b] = (float)(k - start);
                        out[OFF_ACC   + b] = (float)(k + 1);
                    }
                }
            }
            __syncthreads();
            if (!s_cont) break;
            ++k;
        }

        // draft row epilogue: one element per thread
        int dv;
        if (tid < k)        dv = myid;
        else if (tid == k)  dv = s_bonus;
        else                dv = 0;
        out[b * SS + tid] = (float)dv;

    } else {
        // ================= GATHER (speculative) =================
        const int e = (blockIdx.x - NVERIFY) * 1024 + tid;    // [0, 65536)
        if (e < BB * V4) {
            const int b = e / V4;
            const int r = e - b * V4;
            const int start = npa[b] - 1;

            // Speculative read of the overwhelmingly-likely row (num_newly==0).
            // Input is read-only, so this is always safe to issue early.
            float4 spec =
                ((const float4*)(logits + ((size_t)b * SS + (size_t)start) * VV))[r];

            int f;
            do {
                asm volatile("ld.acquire.gpu.b32 %0, [%1];"
                             : "=r"(f) : "l"((int*)&g_ready[b]) : "memory");
                if (!f) __nanosleep(60);
            } while (!f);

            const int pos = g_bonus_pos[b];
            float4 val = (pos == start)
                ? spec
                : ((const float4*)(logits + ((size_t)b * SS + (size_t)pos) * VV))[r];
            ((float4*)(out + OFF_LOGITS))[e] = val;
        }
    }

    // ---- self-cleaning reset: last block out zeroes the handshake state ----
    __syncthreads();
    if (tid == 0) {
        __threadfence();
        int prev = atomicAdd(&g_done, 1);
        if (prev == NBLK - 1) {
            g_done = 0;
            #pragma unroll
            for (int i = 0; i < BB; i++) g_ready[i] = 0;
        }
    }
}

extern "C" void kernel_launch(void* const* d_in, const int* in_sizes, int n_in,
                              void* d_out, int out_size) {
    const int*   input_ids = (const int*)  d_in[0];
    const float* logits    = (const float*)d_in[1];
    const int*   npa       = (const int*)  d_in[2];
    float* out = (float*)d_out;

    eagle_fused_kernel<<<NBLK, 1024>>>(input_ids, logits, npa, out);
}

// round 4
// speedup vs baseline: 1.2362x; 1.2362x over previous
#include <cuda_runtime.h>
#include <math_constants.h>

// Problem constants (B=8, S=1024, V=32000)
#define BB 8
#define SS 1024
#define VV 32000
#define V4 (VV / 4)   // 8000 float4 per logits row

// Output layout (float32, tuple order):
//   [0 .. B*S)               draft        (8192)
//   [B*S .. B*S+B)           num_newly    (8)
//   [B*S+B .. B*S+2B)        num_acc      (8)
//   [B*S+2B .. +B*V)         last_logits  (256000)
#define OFF_NEWLY   (BB * SS)
#define OFF_ACC     (BB * SS + BB)
#define OFF_LOGITS  (BB * SS + 2 * BB)

// One block per batch row. The argmax pass keeps the whole 128KB logits row
// resident in registers (v[8] float4 x 1024 threads); when the verify loop
// terminates at k = bonus_pos, those registers ARE last_logits[b] — stored
// directly, no gather pass and no inter-block handshake needed.
__global__ __launch_bounds__(1024) void eagle_kernel(
    const int*   __restrict__ input_ids,   // [B, S]
    const float* __restrict__ logits,      // [B, S, V]
    const int*   __restrict__ npa,         // [B]
    float*       __restrict__ out)
{
    const int b    = blockIdx.x;
    const int tid  = threadIdx.x;
    const int lane = tid & 31;
    const int warp = tid >> 5;

    __shared__ float s_val[32];
    __shared__ int   s_idx[32];
    __shared__ int   s_cont;
    __shared__ int   s_bonus;

    const int* ids = input_ids + b * SS;

    // Prefetch draft source ids (coalesced 4KB) — overlaps npa load latency.
    int myid = (tid < SS - 1) ? ids[tid + 1] : 0;

    const int start = npa[b] - 1;
    int k = start;

    const bool tail = (tid + 7 * 1024) < V4;   // V4=8000: threads >= 832 skip j=7
    float4 v[8];
    #pragma unroll
    for (int j = 0; j < 8; j++) v[j] = make_float4(0.f, 0.f, 0.f, 0.f);

    for (;;) {
        const float4* row =
            (const float4*)(logits + ((size_t)b * SS + (size_t)k) * VV);
        const int expect = (k < SS - 1) ? ids[k + 1] : -1;

        // ---- front-batched row load (MLP=8), kept for the epilogue ----
        #pragma unroll
        for (int j = 0; j < 7; j++) v[j] = row[tid + j * 1024];
        if (tail) v[7] = row[tid + 7 * 1024];

        // ---- per-thread argmax (first-occurrence tie-break) ----
        float best = -CUDART_INF_F;
        int   bidx = 0x7fffffff;
        #pragma unroll
        for (int j = 0; j < 8; j++) {
            if (j < 7 || tail) {
                const int base = (tid + j * 1024) * 4;
                const float4 w = v[j];
                // increasing index order + strict '>' => first max kept
                if (w.x > best) { best = w.x; bidx = base;     }
                if (w.y > best) { best = w.y; bidx = base + 1; }
                if (w.z > best) { best = w.z; bidx = base + 2; }
                if (w.w > best) { best = w.w; bidx = base + 3; }
            }
        }
        // warp reduce (val desc, idx asc on ties)
        #pragma unroll
        for (int off = 16; off > 0; off >>= 1) {
            float ov = __shfl_down_sync(0xffffffffu, best, off);
            int   oi = __shfl_down_sync(0xffffffffu, bidx, off);
            if (ov > best || (ov == best && oi < bidx)) { best = ov; bidx = oi; }
        }
        if (lane == 0) { s_val[warp] = best; s_idx[warp] = bidx; }
        __syncthreads();

        if (warp == 0) {
            float v0 = s_val[lane];
            int   i0 = s_idx[lane];
            #pragma unroll
            for (int off = 16; off > 0; off >>= 1) {
                float ov = __shfl_down_sync(0xffffffffu, v0, off);
                int   oi = __shfl_down_sync(0xffffffffu, i0, off);
                if (ov > v0 || (ov == v0 && oi < i0)) { v0 = ov; i0 = oi; }
            }
            if (lane == 0) {
                if (k < SS - 1 && i0 == expect) {
                    s_cont = 1;
                } else {
                    s_cont  = 0;
                    s_bonus = i0;
                    out[OFF_NEWLY + b] = (float)(k - start);   // num_newly
                    out[OFF_ACC   + b] = (float)(k + 1);       // num_acc
                }
            }
        }
        __syncthreads();
        if (!s_cont) break;
        ++k;
    }

    // ---- epilogue 1: last_logits[b] = registers from the final iteration ----
    float4* dst = (float4*)(out + OFF_LOGITS) + (size_t)b * V4;
    #pragma unroll
    for (int j = 0; j < 7; j++) dst[tid + j * 1024] = v[j];
    if (tail) dst[tid + 7 * 1024] = v[7];

    // ---- epilogue 2: draft row (one element per thread; S == blockDim) ----
    int dv;
    if (tid < k)        dv = myid;
    else if (tid == k)  dv = s_bonus;
    else                dv = 0;
    out[b * SS + tid] = (float)dv;
}

extern "C" void kernel_launch(void* const* d_in, const int* in_sizes, int n_in,
                              void* d_out, int out_size) {
    const int*   input_ids = (const int*)  d_in[0];
    const float* logits    = (const float*)d_in[1];
    const int*   npa       = (const int*)  d_in[2];
    float* out = (float*)d_out;

    eagle_kernel<<<BB, 1024>>>(input_ids, logits, npa, out);
}